// round 11
// baseline (speedup 1.0000x reference)
#include <cuda_runtime.h>
#include <cuda_bf16.h>
#include <math.h>

// Problem constants (fixed shapes)
#define BB 4
#define HH 1024
#define WW 1920
#define HW (HH * WW)                 // 1,966,080
#define NPIX (BB * HW)               // 7,864,320
#define ALPHA 100.0f
#define EPSN 1e-7f

// Scratch accumulator: [B][H][W][4] channel-interleaved, 16B/pixel.
// Zero-initialized at module load; normalize_kernel re-zeros it every call,
// so every kernel_launch invocation (correctness run + graph replays) sees
// a zeroed accumulator without a separate memset pass.
__device__ __align__(16) float g_acc[(size_t)NPIX * 4];

// ---------------------------------------------------------------------------
// Splat kernel: 1 thread = 4 consecutive x-pixels (W=1920 divisible by 4).
// grid = (HW/4/256, BB); blockIdx.y = batch.
// ---------------------------------------------------------------------------
__global__ void __launch_bounds__(256)
splat_metric_kernel(const float* __restrict__ rgb1,
                    const float* __restrict__ rgb2,
                    const float* __restrict__ flow_t,
                    const float* __restrict__ flow12,
                    float* __restrict__ out_metric)
{
    int t    = blockIdx.x * blockDim.x + threadIdx.x;   // 0 .. HW/4-1
    int b    = blockIdx.y;
    int rem4 = t * 4;                                   // linear pixel idx (mult of 4)
    int y    = rem4 / WW;
    int x4   = rem4 - y * WW;                           // x of first pixel

    const float* f12 = flow12 + (size_t)b * 2 * HW;
    const float* ft  = flow_t + (size_t)b * 2 * HW;
    const float* r1  = rgb1   + (size_t)b * 3 * HW;
    const float* r2  = rgb2   + (size_t)b * 3 * HW;

    // Coalesced vector loads for 4 pixels
    float4 fxv = *(const float4*)(f12 + rem4);           // flow12.x
    float4 fyv = *(const float4*)(f12 + HW + rem4);      // flow12.y
    float4 gxv = *(const float4*)(ft  + rem4);           // flow_t.x
    float4 gyv = *(const float4*)(ft  + HW + rem4);      // flow_t.y
    float4 c0v = *(const float4*)(r1  + rem4);
    float4 c1v = *(const float4*)(r1  + HW + rem4);
    float4 c2v = *(const float4*)(r1  + 2 * HW + rem4);

    float fx[4] = {fxv.x, fxv.y, fxv.z, fxv.w};
    float fy[4] = {fyv.x, fyv.y, fyv.z, fyv.w};
    float gx[4] = {gxv.x, gxv.y, gxv.z, gxv.w};
    float gy[4] = {gyv.x, gyv.y, gyv.z, gyv.w};
    float c0[4] = {c0v.x, c0v.y, c0v.z, c0v.w};
    float c1[4] = {c1v.x, c1v.y, c1v.z, c1v.w};
    float c2[4] = {c2v.x, c2v.y, c2v.z, c2v.w};

    float met[4];
    float* acc = g_acc + (size_t)b * HW * 4;

    #pragma unroll
    for (int k = 0; k < 4; k++) {
        // ---- Backwarp gather (bilinear, zeros padding) ----
        float px  = (float)(x4 + k) + fx[k];
        float py  = (float)y        + fy[k];
        float x0f = floorf(px), y0f = floorf(py);
        int   x0  = (int)x0f,   y0  = (int)y0f;
        float wx  = px - x0f,   wy  = py - y0f;

        float bw0 = 0.f, bw1 = 0.f, bw2 = 0.f;
        float wtx[2] = {1.f - wx, wx};
        float wty[2] = {1.f - wy, wy};
        #pragma unroll
        for (int ty = 0; ty < 2; ty++) {
            int yi = y0 + ty;
            if (yi < 0 || yi >= HH) continue;
            #pragma unroll
            for (int tx = 0; tx < 2; tx++) {
                int xi = x0 + tx;
                if (xi < 0 || xi >= WW) continue;
                float w   = wtx[tx] * wty[ty];
                int   idx = yi * WW + xi;
                bw0 += w * __ldg(r2 + idx);
                bw1 += w * __ldg(r2 + HW + idx);
                bw2 += w * __ldg(r2 + 2 * HW + idx);
            }
        }

        // ---- Metric + weight ----
        float metric = (fabsf(c0[k] - bw0) + fabsf(c1[k] - bw1) + fabsf(c2[k] - bw2))
                       * (1.0f / 3.0f);
        met[k] = metric;
        float m  = fminf(fmaxf(-ALPHA * metric, -ALPHA), ALPHA);
        float em = __expf(m);

        // ---- Forward splat (bilinear scatter-add) ----
        float qx   = (float)(x4 + k) + gx[k];
        float qy   = (float)y        + gy[k];
        float qx0f = floorf(qx), qy0f = floorf(qy);
        int   qx0  = (int)qx0f,  qy0  = (int)qy0f;
        float ux   = qx - qx0f,  uy   = qy - qy0f;

        float v0 = c0[k] * em, v1 = c1[k] * em, v2 = c2[k] * em;

        float utx[2] = {1.f - ux, ux};
        float uty[2] = {1.f - uy, uy};
        #pragma unroll
        for (int ty = 0; ty < 2; ty++) {
            int yi = qy0 + ty;
            if (yi < 0 || yi >= HH) continue;
            #pragma unroll
            for (int tx = 0; tx < 2; tx++) {
                int xi = qx0 + tx;
                if (xi < 0 || xi >= WW) continue;
                float w = utx[tx] * uty[ty];
                float4* p = (float4*)(acc + (size_t)(yi * WW + xi) * 4);
                atomicAdd(p, make_float4(v0 * w, v1 * w, v2 * w, em * w));
            }
        }
    }

    *(float4*)(out_metric + (size_t)b * HW + rem4) = make_float4(met[0], met[1], met[2], met[3]);
}

// ---------------------------------------------------------------------------
// Normalize kernel: 1 thread = 4 pixels. Reads 64B of acc, re-zeros it,
// writes one float4 per output plane.
// grid = (HW/4/256, BB)
// ---------------------------------------------------------------------------
__global__ void __launch_bounds__(256)
normalize_kernel(float* __restrict__ out_img)
{
    int t    = blockIdx.x * blockDim.x + threadIdx.x;   // 0 .. HW/4-1
    int b    = blockIdx.y;
    int rem4 = t * 4;

    float4* accp = (float4*)(g_acc + ((size_t)b * HW + rem4) * 4);
    float4 a0 = accp[0];
    float4 a1 = accp[1];
    float4 a2 = accp[2];
    float4 a3 = accp[3];

    // Re-zero accumulator for the next invocation (replaces the memset pass)
    float4 z = make_float4(0.f, 0.f, 0.f, 0.f);
    accp[0] = z; accp[1] = z; accp[2] = z; accp[3] = z;

    float i0 = 1.0f / (a0.w + EPSN);
    float i1 = 1.0f / (a1.w + EPSN);
    float i2 = 1.0f / (a2.w + EPSN);
    float i3 = 1.0f / (a3.w + EPSN);

    float* o = out_img + (size_t)b * 3 * HW;
    *(float4*)(o + rem4)          = make_float4(a0.x * i0, a1.x * i1, a2.x * i2, a3.x * i3);
    *(float4*)(o + HW + rem4)     = make_float4(a0.y * i0, a1.y * i1, a2.y * i2, a3.y * i3);
    *(float4*)(o + 2 * HW + rem4) = make_float4(a0.z * i0, a1.z * i1, a2.z * i2, a3.z * i3);
}

extern "C" void kernel_launch(void* const* d_in, const int* in_sizes, int n_in,
                              void* d_out, int out_size)
{
    const float* rgb1   = (const float*)d_in[0];
    const float* rgb2   = (const float*)d_in[1];
    const float* flow_t = (const float*)d_in[2];  // flow_src1_to_tgt
    const float* flow12 = (const float*)d_in[3];  // flow_src1_to_src2

    float* out_img    = (float*)d_out;                        // [B,3,H,W]
    float* out_metric = (float*)d_out + (size_t)BB * 3 * HW;  // [B,1,H,W]

    const int threads = 256;
    dim3 grid((HW / 4 + threads - 1) / threads, BB);

    splat_metric_kernel<<<grid, threads, 0, 0>>>(rgb1, rgb2, flow_t, flow12, out_metric);
    normalize_kernel<<<grid, threads, 0, 0>>>(out_img);
}